// round 10
// baseline (speedup 1.0000x reference)
#include <cuda_runtime.h>
#include <cuda_bf16.h>
#include <cstdint>

#define B_   8
#define S_   1024
#define H_   1024
#define NH_  4
#define D_   256
#define MROWS (B_*S_)                 // 8192
#define OUT0  ((size_t)MROWS*H_)      // start of attn region in d_out

#define BM 128
#define BN 128
#define BK 16        // tf32 loop k-tile
#define PAD 4
#define BK2 32       // bf16 loop k-tile
#define AD 40        // bf16 smem row stride (80B, 16B-aligned rows, 5 coprime 8)

// Scratch (device globals: no allocation allowed)
__device__ float g_Q[MROWS*H_];
__device__ float g_K[MROWS*H_];
__device__ float g_V[MROWS*H_];
__device__ float g_res[MROWS*H_];
__device__ float g_tmp[MROWS*H_];
__device__ float g_rowsum[NH_*B_*S_];
__device__ float g_WT[3*H_*H_];       // Wk^T, Wv^T, Wq^T  ([n][k])
__device__ float g_WfT[H_*2*H_];      // Wf^T  [n=1024][k=2048]
__device__ float g_P[(size_t)NH_*B_*S_*S_];   // unnormalized attention weights

// ---------------- helpers ----------------

__device__ __forceinline__ uint32_t su32(const void* p){
    return (uint32_t)__cvta_generic_to_shared(p);
}

__device__ __forceinline__ float tf32r(float x){
    uint32_t u;
    asm("cvt.rna.tf32.f32 %0, %1;" : "=r"(u) : "f"(x));
    return __uint_as_float(u);
}

__device__ __forceinline__ void mma8(float c[4], const uint32_t a[4], const uint32_t b[2]){
    asm volatile(
      "mma.sync.aligned.m16n8k8.row.col.f32.tf32.tf32.f32 "
      "{%0,%1,%2,%3}, {%4,%5,%6,%7}, {%8,%9}, {%0,%1,%2,%3};\n"
      : "+f"(c[0]), "+f"(c[1]), "+f"(c[2]), "+f"(c[3])
      : "r"(a[0]), "r"(a[1]), "r"(a[2]), "r"(a[3]), "r"(b[0]), "r"(b[1]));
}

__device__ __forceinline__ void mma16(float c[4], const uint32_t a[4], const uint32_t b[2]){
    asm volatile(
      "mma.sync.aligned.m16n8k16.row.col.f32.bf16.bf16.f32 "
      "{%0,%1,%2,%3}, {%4,%5,%6,%7}, {%8,%9}, {%0,%1,%2,%3};\n"
      : "+f"(c[0]), "+f"(c[1]), "+f"(c[2]), "+f"(c[3])
      : "r"(a[0]), "r"(a[1]), "r"(a[2]), "r"(a[3]), "r"(b[0]), "r"(b[1]));
}

__device__ __forceinline__ void ldsm4(uint32_t r[4], uint32_t a){
    asm volatile("ldmatrix.sync.aligned.m8n8.x4.shared.b16 {%0,%1,%2,%3}, [%4];\n"
      : "=r"(r[0]), "=r"(r[1]), "=r"(r[2]), "=r"(r[3]) : "r"(a));
}

__device__ __forceinline__ uint32_t pack2(__nv_bfloat16 e, __nv_bfloat16 o){
    return (uint32_t)__bfloat16_as_ushort(e) | ((uint32_t)__bfloat16_as_ushort(o) << 16);
}

// ---- bf3 tile prefetch / convert+store (128x32 fp32 tile, k contiguous) ----

__device__ __forceinline__ void pref_tile(
    const float* __restrict__ src, int lds, int kofs, float4 p[4], int tid)
{
    #pragma unroll
    for (int j = 0; j < 4; j++){
        int id  = tid + j*256;
        int row = id >> 3;
        int kq  = (id & 7) * 4;
        p[j] = *reinterpret_cast<const float4*>(src + (size_t)row*lds + kofs + kq);
    }
}

__device__ __forceinline__ void cvt_tile(
    const float4 p[4], __nv_bfloat16 (*H)[AD], __nv_bfloat16 (*L)[AD], int tid)
{
    #pragma unroll
    for (int j = 0; j < 4; j++){
        int id  = tid + j*256;
        int row = id >> 3;
        int kq  = (id & 7) * 4;
        float4 v = p[j];
        __nv_bfloat16 h0 = __float2bfloat16_rn(v.x);
        __nv_bfloat16 h1 = __float2bfloat16_rn(v.y);
        __nv_bfloat16 h2 = __float2bfloat16_rn(v.z);
        __nv_bfloat16 h3 = __float2bfloat16_rn(v.w);
        __nv_bfloat16 l0 = __float2bfloat16_rn(v.x - __bfloat162float(h0));
        __nv_bfloat16 l1 = __float2bfloat16_rn(v.y - __bfloat162float(h1));
        __nv_bfloat16 l2 = __float2bfloat16_rn(v.z - __bfloat162float(h2));
        __nv_bfloat16 l3 = __float2bfloat16_rn(v.w - __bfloat162float(h3));
        uint2 Hp, Lp;
        Hp.x = pack2(h0, h1); Hp.y = pack2(h2, h3);
        Lp.x = pack2(l0, l1); Lp.y = pack2(l2, l3);
        *reinterpret_cast<uint2*>(&H[row][kq]) = Hp;
        *reinterpret_cast<uint2*>(&L[row][kq]) = Lp;
    }
}

// 3xBF16 split GEMM with register-prefetch pipelining.
// C += A @ B^T ; A: (m,k) at A[m*lda+k], B: (n,k) at Bm[n*ldb+k].
__device__ __forceinline__ void gemm_bf3(
    const float* __restrict__ A, int lda,
    const float* __restrict__ Bm, int ldb,
    int kTiles, float acc[4][4][4],
    __nv_bfloat16 (*Ah)[AD], __nv_bfloat16 (*Al)[AD],
    __nv_bfloat16 (*Bh)[AD], __nv_bfloat16 (*Bl)[AD])
{
    const int tid  = threadIdx.x;
    const int lane = tid & 31, warp = tid >> 5;
    const int wm = (warp >> 2) * 64, wn = (warp & 3) * 32;

    const uint32_t aH = su32(&Ah[0][0]), aL = su32(&Al[0][0]);
    const uint32_t bH = su32(&Bh[0][0]), bL = su32(&Bl[0][0]);
    // combined hi/lo B ldsm4: lanes 0-15 fetch from Bh, lanes 16-31 from Bl
    const uint32_t bSel = (lane & 16) ? bL : bH;

    const int rowA = wm + ((lane >> 3) & 1) * 8 + (lane & 7);
    const int kcA  = (lane >> 4) * 8;
    const int rowB = (lane & 7);
    const int kcB  = ((lane >> 3) & 1) * 8;

    float4 pa[4], pb[4];
    pref_tile(A,  lda, 0, pa, tid);
    pref_tile(Bm, ldb, 0, pb, tid);
    cvt_tile(pa, Ah, Al, tid);
    cvt_tile(pb, Bh, Bl, tid);
    __syncthreads();

    for (int kt = 0; kt < kTiles; kt++){
        const bool more = (kt + 1 < kTiles);
        if (more){
            pref_tile(A,  lda, (kt+1)*BK2, pa, tid);
            pref_tile(Bm, ldb, (kt+1)*BK2, pb, tid);
        }

        #pragma unroll
        for (int s = 0; s < 2; s++){
            int kw = s * 16;
            uint32_t br[4][4];
            #pragma unroll
            for (int nt = 0; nt < 4; nt++){
                uint32_t off = (uint32_t)(((wn + nt*8 + rowB)*AD + kw + kcB) * 2);
                ldsm4(br[nt], bSel + off);    // br[0..1]=bh, br[2..3]=bl
            }
            #pragma unroll
            for (int mt = 0; mt < 4; mt++){
                uint32_t off = (uint32_t)(((rowA + mt*16)*AD + kw + kcA) * 2);
                uint32_t ah[4], al[4];
                ldsm4(ah, aH + off);
                ldsm4(al, aL + off);
                #pragma unroll
                for (int nt = 0; nt < 4; nt++){
                    mma16(acc[mt][nt], ah, &br[nt][0]);
                    mma16(acc[mt][nt], ah, &br[nt][2]);
                    mma16(acc[mt][nt], al, &br[nt][0]);
                }
            }
        }
        __syncthreads();
        if (more){
            cvt_tile(pa, Ah, Al, tid);
            cvt_tile(pb, Bh, Bl, tid);
            __syncthreads();
        }
    }
}

// Single-TF32 GEMM with register-prefetch pipelining. If Pout != nullptr, the
// A store-phase also writes original fp32 A values scaled by sc0/sc1 to Pout.
template<bool TRANSB>
__device__ __forceinline__ void gemm_tf32(
    const float* __restrict__ A, int lda,
    const float* __restrict__ Bm, int ldb,
    int kTiles, float acc[4][4][4],
    float As[BK][BM+PAD], float Bs[BK][BN+PAD],
    float* __restrict__ Pout = nullptr, float sc0 = 0.f, float sc1 = 0.f)
{
    const int tid  = threadIdx.x;
    const int lane = tid & 31, warp = tid >> 5;
    const int wm = (warp >> 2) * 64, wn = (warp & 3) * 32;
    const int g  = lane >> 2;

    const int arow = tid >> 2, acg = (tid & 3) * 4;

    float4 pa[2], pb[2];

    auto prefA = [&](int k0){
        #pragma unroll
        for (int i = 0; i < 2; i++)
            pa[i] = *reinterpret_cast<const float4*>(A + (size_t)(arow + i*64)*lda + k0 + acg);
    };
    auto prefB = [&](int k0){
        #pragma unroll
        for (int i = 0; i < 2; i++){
            int idx = tid + i*256;
            if (!TRANSB){
                int row = idx >> 5, cg = (idx & 31) * 4;
                pb[i] = *reinterpret_cast<const float4*>(Bm + (size_t)(k0 + row)*ldb + cg);
            } else {
                int n = idx >> 2, kg = (idx & 3) * 4;
                pb[i] = *reinterpret_cast<const float4*>(Bm + (size_t)n*ldb + k0 + kg);
            }
        }
    };
    auto storeA = [&](int k0){
        #pragma unroll
        for (int i = 0; i < 2; i++){
            int row = arow + i*64;
            float4 v = pa[i];
            if (Pout){
                float sc = i ? sc1 : sc0;
                float4 w; w.x = v.x*sc; w.y = v.y*sc; w.z = v.z*sc; w.w = v.w*sc;
                *reinterpret_cast<float4*>(Pout + (size_t)row*lda + k0 + acg) = w;
            }
            As[acg+0][row] = tf32r(v.x);
            As[acg+1][row] = tf32r(v.y);
            As[acg+2][row] = tf32r(v.z);
            As[acg+3][row] = tf32r(v.w);
        }
    };
    auto storeB = [&](){
        #pragma unroll
        for (int i = 0; i < 2; i++){
            int idx = tid + i*256;
            float4 v = pb[i];
            if (!TRANSB){
                int row = idx >> 5, cg = (idx & 31) * 4;
                Bs[row][cg+0] = tf32r(v.x);
                Bs[row][cg+1] = tf32r(v.y);
                Bs[row][cg+2] = tf32r(v.z);
                Bs[row][cg+3] = tf32r(v.w);
            } else {
                int n = idx >> 2, kg = (idx & 3) * 4;
                Bs[kg+0][n] = tf32r(v.x);
                Bs[kg+1][n] = tf32r(v.y);
                Bs[kg+2][n] = tf32r(v.z);
                Bs[kg+3][n] = tf32r(v.w);
            }
        }
    };

    prefA(0); prefB(0);
    storeA(0); storeB();
    __syncthreads();

    for (int kt = 0; kt < kTiles; kt++){
        const bool more = (kt + 1 < kTiles);
        if (more){ prefA((kt+1)*BK); prefB((kt+1)*BK); }

        #pragma unroll
        for (int ks = 0; ks < 2; ks++){
            int kr = ks*8 + (lane & 3);
            uint32_t af[4][4], bfr[4][2];
            #pragma unroll
            for (int mt = 0; mt < 4; mt++){
                int r = wm + mt*16 + g;
                af[mt][0] = __float_as_uint(As[kr  ][r  ]);
                af[mt][1] = __float_as_uint(As[kr  ][r+8]);
                af[mt][2] = __float_as_uint(As[kr+4][r  ]);
                af[mt][3] = __float_as_uint(As[kr+4][r+8]);
            }
            #pragma unroll
            for (int nt = 0; nt < 4; nt++){
                int c = wn + nt*8 + g;
                bfr[nt][0] = __float_as_uint(Bs[kr  ][c]);
                bfr[nt][1] = __float_as_uint(Bs[kr+4][c]);
            }
            #pragma unroll
            for (int mt = 0; mt < 4; mt++)
                #pragma unroll
                for (int nt = 0; nt < 4; nt++)
                    mma8(acc[mt][nt], af[mt], bfr[nt]);
        }
        __syncthreads();
        if (more){
            storeA((kt+1)*BK); storeB();
            __syncthreads();
        }
    }
}

// ---------------- kernels ----------------

__global__ void __launch_bounds__(256) k_zero(){
    g_rowsum[blockIdx.x*blockDim.x + threadIdx.x] = 0.0f;
}

// Transpose weights: z<3 -> Wk/Wv/Wq (1024x1024) -> g_WT[z]; z=3,4 -> Wf halves -> g_WfT [1024][2048]
__global__ void __launch_bounds__(256) k_tr(
    const float* __restrict__ Wk, const float* __restrict__ Wv,
    const float* __restrict__ Wq, const float* __restrict__ Wf)
{
    __shared__ float t[32][33];
    int z = blockIdx.z;
    const float* src; float* dst; int ldd, koff;
    if (z < 3){
        src = (z == 0) ? Wk : (z == 1 ? Wv : Wq);
        dst = g_WT + (size_t)z * H_ * H_;
        ldd = H_; koff = 0;
    } else {
        src = Wf + (size_t)(z-3) * H_ * H_;
        dst = g_WfT;
        ldd = 2*H_; koff = (z-3) * H_;
    }
    int x  = blockIdx.x*32 + threadIdx.x;   // n
    int y0 = blockIdx.y*32;                 // k
    #pragma unroll
    for (int j = 0; j < 4; j++)
        t[threadIdx.y + 8*j][threadIdx.x] = src[(size_t)(y0 + threadIdx.y + 8*j)*H_ + x];
    __syncthreads();
    #pragma unroll
    for (int j = 0; j < 4; j++){
        int n = blockIdx.x*32 + threadIdx.y + 8*j;
        dst[(size_t)n*ldd + koff + y0 + threadIdx.x] = t[threadIdx.x][threadIdx.y + 8*j];
    }
}

// z=0: K = memory@Wk ; z=1: V = memory@Wv ; z=2: Q = decoder@Wq   (bf16x3, B = W^T)
__global__ void __launch_bounds__(256, 1) k_qkv(
    const float* __restrict__ mem, const float* __restrict__ dec)
{
    __shared__ __nv_bfloat16 Ah[128][AD], Al[128][AD], Bh[128][AD], Bl[128][AD];
    float acc[4][4][4] = {};

    int m0 = blockIdx.y * BM, n0 = blockIdx.x * BN;
    const float* A = (blockIdx.z == 2) ? dec : mem;
    float* C = (blockIdx.z == 0) ? g_K : (blockIdx.z == 1 ? g_V : g_Q);
    const float* Bt = g_WT + (size_t)blockIdx.z * H_ * H_ + (size_t)n0 * H_;

    gemm_bf3(A + (size_t)m0*H_, H_, Bt, H_, H_/BK2, acc, Ah, Al, Bh, Bl);

    const int lane = threadIdx.x & 31, warp = threadIdx.x >> 5;
    const int wm = (warp>>2)*64, wn = (warp&3)*32, g = lane>>2, cq = (lane&3)*2;
    #pragma unroll
    for (int mt = 0; mt < 4; mt++)
      #pragma unroll
      for (int nt = 0; nt < 4; nt++)
        #pragma unroll
        for (int r = 0; r < 4; r++){
            int rl = wm + mt*16 + g + ((r>>1)<<3);
            int cl = wn + nt*8 + cq + (r&1);
            C[(size_t)(m0+rl)*H_ + n0 + cl] = acc[mt][nt][r];
        }
}

// S = Q@K^T/16 - gauss ; mask -> p=0 ; p = exp(s) unnormalized -> g_P; rowsum atomics (bf16x3)
__global__ void __launch_bounds__(256, 1) k_score(
    const int* __restrict__ mask,
    const float* __restrict__ gfac)
{
    __shared__ __nv_bfloat16 Ah[128][AD], Al[128][AD], Bh[128][AD], Bl[128][AD];
    float acc[4][4][4] = {};

    int hb = blockIdx.z, h = hb >> 3, b = hb & 7;
    int q0 = blockIdx.y * BM, n0 = blockIdx.x * BN;

    const float* Aq = g_Q + (size_t)(b*S_)*H_ + h*D_ + (size_t)q0*H_;
    const float* Bk = g_K + (size_t)(b*S_)*H_ + h*D_ + (size_t)n0*H_;
    gemm_bf3(Aq, H_, Bk, H_, D_/BK2, acc, Ah, Al, Bh, Bl);

    float inv_gf = 1.0f / gfac[0];
    float* out = g_P + (size_t)hb * S_ * S_;
    const int* mrow = mask + (size_t)b * S_ * S_;

    const int lane = threadIdx.x & 31, warp = threadIdx.x >> 5;
    const int wm = (warp>>2)*64, wn = (warp&3)*32, g = lane>>2, cq = (lane&3)*2;
    #pragma unroll
    for (int mt = 0; mt < 4; mt++){
        float rs[2] = {0.0f, 0.0f};
        #pragma unroll
        for (int nt = 0; nt < 4; nt++)
            #pragma unroll
            for (int r = 0; r < 4; r++){
                int row = q0 + wm + mt*16 + g + ((r>>1)<<3);
                int col = n0 + wn + nt*8 + cq + (r&1);
                int dq  = row - col;
                float s = acc[mt][nt][r]*0.0625f - (float)(dq*dq)*inv_gf;
                float p = mrow[(size_t)row*S_ + col] ? 0.0f : __expf(s);
                out[(size_t)row*S_ + col] = p;
                rs[r>>1] += p;
            }
        #pragma unroll
        for (int j = 0; j < 2; j++){
            rs[j] += __shfl_xor_sync(0xffffffffu, rs[j], 1);
            rs[j] += __shfl_xor_sync(0xffffffffu, rs[j], 2);
        }
        if ((lane & 3) == 0){
            int rbase = hb*S_ + q0 + wm + mt*16 + g;
            atomicAdd(&g_rowsum[rbase    ], rs[0]);
            atomicAdd(&g_rowsum[rbase + 8], rs[1]);
        }
    }
}

// O = P@V (tf32), epilogue scale by query_mask/rowsum -> g_res.
// n0==0 blocks also stream normalized attention to d_out (fused into A loads).
__global__ void __launch_bounds__(256, 1) k_pv(
    const float* __restrict__ qm, float* __restrict__ attn)
{
    __shared__ __align__(16) float As[BK][BM+PAD];
    __shared__ __align__(16) float Bs[BK][BN+PAD];
    float acc[4][4][4] = {};

    int hb = blockIdx.z, h = hb >> 3, b = hb & 7;
    int q0 = blockIdx.y * BM, n0 = blockIdx.x * BN;   // n over D (=256)

    const float* Ap = g_P + (size_t)hb*S_*S_ + (size_t)q0*S_;
    const float* Bv = g_V + (size_t)(b*S_)*H_ + h*D_ + n0;

    float* Pout = nullptr; float sc0 = 0.f, sc1 = 0.f;
    if (n0 == 0){
        Pout = attn + (size_t)hb*S_*S_ + (size_t)q0*S_;
        int r0 = (threadIdx.x >> 2), r1 = r0 + 64;
        sc0 = qm[b*S_ + q0 + r0] / g_rowsum[hb*S_ + q0 + r0];
        sc1 = qm[b*S_ + q0 + r1] / g_rowsum[hb*S_ + q0 + r1];
    }

    gemm_tf32<false>(Ap, S_, Bv, H_, S_/BK, acc, As, Bs, Pout, sc0, sc1);

    const int lane = threadIdx.x & 31, warp = threadIdx.x >> 5;
    const int wm = (warp>>2)*64, wn = (warp&3)*32, g = lane>>2, cq = (lane&3)*2;
    #pragma unroll
    for (int mt = 0; mt < 4; mt++)
      #pragma unroll
      for (int r2 = 0; r2 < 2; r2++){
          int q  = q0 + wm + mt*16 + g + r2*8;
          float sc = qm[b*S_ + q] / g_rowsum[hb*S_ + q];
          #pragma unroll
          for (int nt = 0; nt < 4; nt++)
            #pragma unroll
            for (int rr = 0; rr < 2; rr++){
                int cl = wn + nt*8 + cq + rr;
                g_res[(size_t)(b*S_+q)*H_ + h*D_ + n0 + cl] = acc[mt][nt][r2*2+rr]*sc;
            }
      }
}

// out_pre_ln = [decoder | res] @ Wf + bf + decoder -> g_tmp   (tf32, B = Wf^T)
__global__ void __launch_bounds__(256, 1) k_final(
    const float* __restrict__ dec, const float* __restrict__ bfv)
{
    __shared__ __align__(16) float As[BK][BM+PAD];
    __shared__ __align__(16) float Bs[BK][BN+PAD];
    float acc[4][4][4] = {};

    int m0 = blockIdx.y * BM, n0 = blockIdx.x * BN;
    gemm_tf32<true>(dec   + (size_t)m0*H_, H_, g_WfT + (size_t)n0*2*H_,       2*H_, H_/BK, acc, As, Bs);
    gemm_tf32<true>(g_res + (size_t)m0*H_, H_, g_WfT + (size_t)n0*2*H_ + H_,  2*H_, H_/BK, acc, As, Bs);

    const int lane = threadIdx.x & 31, warp = threadIdx.x >> 5;
    const int wm = (warp>>2)*64, wn = (warp&3)*32, g = lane>>2, cq = (lane&3)*2;
    #pragma unroll
    for (int mt = 0; mt < 4; mt++)
      #pragma unroll
      for (int nt = 0; nt < 4; nt++)
        #pragma unroll
        for (int r = 0; r < 4; r++){
            int rl = wm + mt*16 + g + ((r>>1)<<3);
            int cl = wn + nt*8 + cq + (r&1);
            size_t idx = (size_t)(m0+rl)*H_ + n0 + cl;
            g_tmp[idx] = acc[mt][nt][r] + bfv[n0+cl] + dec[idx];
        }
}

// per-row layernorm over H=1024 -> d_out
__global__ void __launch_bounds__(256) k_ln(
    const float* __restrict__ gam, const float* __restrict__ bet,
    float* __restrict__ out)
{
    __shared__ float red[8];
    int row = blockIdx.x, tid = threadIdx.x;
    float4 v = reinterpret_cast<const float4*>(g_tmp + (size_t)row*H_)[tid];
    float s = v.x + v.y + v.z + v.w;
    #pragma unroll
    for (int o = 16; o; o >>= 1) s += __shfl_xor_sync(0xffffffffu, s, o);
    if ((tid & 31) == 0) red[tid >> 5] = s;
    __syncthreads();
    float tot = 0.0f;
    #pragma unroll
    for (int i = 0; i < 8; i++) tot += red[i];
    float mu = tot * (1.0f/H_);
    float dx = v.x - mu, dy = v.y - mu, dz = v.z - mu, dw = v.w - mu;
    float s2 = dx*dx + dy*dy + dz*dz + dw*dw;
    #pragma unroll
    for (int o = 16; o; o >>= 1) s2 += __shfl_xor_sync(0xffffffffu, s2, o);
    __syncthreads();
    if ((tid & 31) == 0) red[tid >> 5] = s2;
    __syncthreads();
    float tot2 = 0.0f;
    #pragma unroll
    for (int i = 0; i < 8; i++) tot2 += red[i];
    float inv = rsqrtf(tot2 * (1.0f/H_) + 1e-5f);
    int c = tid * 4;
    float4 o4;
    o4.x = dx*inv*gam[c+0] + bet[c+0];
    o4.y = dy*inv*gam[c+1] + bet[c+1];
    o4.z = dz*inv*gam[c+2] + bet[c+2];
    o4.w = dw*inv*gam[c+3] + bet[c+3];
    reinterpret_cast<float4*>(out + (size_t)row*H_)[tid] = o4;
}

extern "C" void kernel_launch(void* const* d_in, const int* in_sizes, int n_in,
                              void* d_out, int out_size)
{
    (void)in_sizes; (void)n_in; (void)out_size;
    const float* memory = (const float*)d_in[0];
    const float* dec    = (const float*)d_in[1];
    const int*   mask   = (const int*)d_in[2];    // bool stored as int32
    const float* qmask  = (const float*)d_in[3];
    const float* Wk     = (const float*)d_in[4];
    const float* Wv     = (const float*)d_in[5];
    const float* Wq     = (const float*)d_in[6];
    const float* Wf     = (const float*)d_in[7];
    const float* bfv    = (const float*)d_in[8];
    const float* gamma  = (const float*)d_in[9];
    const float* beta   = (const float*)d_in[10];
    const float* gfac   = (const float*)d_in[11];

    float* out  = (float*)d_out;
    float* attn = out + OUT0;

    k_tr<<<dim3(32, 32, 5), dim3(32, 8)>>>(Wk, Wv, Wq, Wf);
    k_zero<<<128, 256>>>();
    k_qkv<<<dim3(8, 64, 3), 256>>>(memory, dec);
    k_score<<<dim3(8, 8, 32), 256>>>(mask, gfac);
    k_pv<<<dim3(2, 8, 32), 256>>>(qmask, attn);
    k_final<<<dim3(8, 64), 256>>>(dec, bfv);
    k_ln<<<8192, 256>>>(gamma, beta, out);
}

// round 12
// speedup vs baseline: 1.4671x; 1.4671x over previous
#include <cuda_runtime.h>
#include <cuda_bf16.h>
#include <cstdint>

#define B_   8
#define S_   1024
#define H_   1024
#define NH_  4
#define D_   256
#define MROWS (B_*S_)                 // 8192
#define OUT0  ((size_t)MROWS*H_)      // start of attn region in d_out

#define BM 128
#define BN 128
#define BK2 32       // bf16 loop k-tile
#define AD 40        // bf16 smem row stride
#define TKT 16       // tf32 cp.async k-tile
#define TST 20       // tf32 smem row stride (floats): 80B rows, r*5 mod 8 distinct

// Scratch (device globals: no allocation allowed)
__device__ float g_Q[MROWS*H_];
__device__ float g_K[MROWS*H_];
__device__ float g_V[MROWS*H_];
__device__ float g_VT[MROWS*H_];      // V^T per (b,h): [(b*NH+h)*D + d][s], tf32-rounded
__device__ float g_res[MROWS*H_];
__device__ float g_tmp[MROWS*H_];
__device__ float g_rowsum[NH_*B_*S_];
__device__ float g_WT[3*H_*H_];       // Wk^T, Wv^T, Wq^T ([n][k], fp32 for bf3 split)
__device__ float g_WfT[H_*2*H_];      // Wf^T [n=1024][k=2048], tf32-rounded

// ---------------- helpers ----------------

__device__ __forceinline__ uint32_t su32(const void* p){
    return (uint32_t)__cvta_generic_to_shared(p);
}
__device__ __forceinline__ float tf32r(float x){
    uint32_t u;
    asm("cvt.rna.tf32.f32 %0, %1;" : "=r"(u) : "f"(x));
    return __uint_as_float(u);
}
__device__ __forceinline__ void mma8(float c[4], const uint32_t a[4], const uint32_t b[2]){
    asm volatile(
      "mma.sync.aligned.m16n8k8.row.col.f32.tf32.tf32.f32 "
      "{%0,%1,%2,%3}, {%4,%5,%6,%7}, {%8,%9}, {%0,%1,%2,%3};\n"
      : "+f"(c[0]), "+f"(c[1]), "+f"(c[2]), "+f"(c[3])
      : "r"(a[0]), "r"(a[1]), "r"(a[2]), "r"(a[3]), "r"(b[0]), "r"(b[1]));
}
__device__ __forceinline__ void mma16(float c[4], const uint32_t a[4], const uint32_t b[2]){
    asm volatile(
      "mma.sync.aligned.m16n8k16.row.col.f32.bf16.bf16.f32 "
      "{%0,%1,%2,%3}, {%4,%5,%6,%7}, {%8,%9}, {%0,%1,%2,%3};\n"
      : "+f"(c[0]), "+f"(c[1]), "+f"(c[2]), "+f"(c[3])
      : "r"(a[0]), "r"(a[1]), "r"(a[2]), "r"(a[3]), "r"(b[0]), "r"(b[1]));
}
__device__ __forceinline__ void ldsm4(uint32_t r[4], uint32_t a){
    asm volatile("ldmatrix.sync.aligned.m8n8.x4.shared.b16 {%0,%1,%2,%3}, [%4];\n"
      : "=r"(r[0]), "=r"(r[1]), "=r"(r[2]), "=r"(r[3]) : "r"(a));
}
__device__ __forceinline__ void ldsm2(uint32_t r[2], uint32_t a){
    asm volatile("ldmatrix.sync.aligned.m8n8.x2.shared.b16 {%0,%1}, [%2];\n"
      : "=r"(r[0]), "=r"(r[1]) : "r"(a));
}
__device__ __forceinline__ void cpa16(uint32_t dst, const void* src){
    asm volatile("cp.async.cg.shared.global [%0], [%1], 16;\n" :: "r"(dst), "l"(src));
}
__device__ __forceinline__ void cp_commit(){ asm volatile("cp.async.commit_group;\n"); }
template<int N> __device__ __forceinline__ void cp_wait(){
    asm volatile("cp.async.wait_group %0;\n" :: "n"(N));
}
__device__ __forceinline__ uint32_t pack2(__nv_bfloat16 e, __nv_bfloat16 o){
    return (uint32_t)__bfloat16_as_ushort(e) | ((uint32_t)__bfloat16_as_ushort(o) << 16);
}

// ---- bf3 tile load (128x32 fp32 tile, k contiguous) -> bf16 hi/lo smem planes ----
__device__ __forceinline__ void load_tile_bf(
    const float* __restrict__ src, int lds, int kofs,
    __nv_bfloat16 (*Hh)[AD], __nv_bfloat16 (*Ll)[AD], int tid)
{
    #pragma unroll
    for (int j = 0; j < 4; j++){
        int id  = tid + j*256;
        int row = id >> 3;
        int kq  = (id & 7) * 4;
        float4 v = *reinterpret_cast<const float4*>(src + (size_t)row*lds + kofs + kq);
        __nv_bfloat16 h0 = __float2bfloat16_rn(v.x);
        __nv_bfloat16 h1 = __float2bfloat16_rn(v.y);
        __nv_bfloat16 h2 = __float2bfloat16_rn(v.z);
        __nv_bfloat16 h3 = __float2bfloat16_rn(v.w);
        __nv_bfloat16 l0 = __float2bfloat16_rn(v.x - __bfloat162float(h0));
        __nv_bfloat16 l1 = __float2bfloat16_rn(v.y - __bfloat162float(h1));
        __nv_bfloat16 l2 = __float2bfloat16_rn(v.z - __bfloat162float(h2));
        __nv_bfloat16 l3 = __float2bfloat16_rn(v.w - __bfloat162float(h3));
        uint2 Hp, Lp;
        Hp.x = pack2(h0, h1); Hp.y = pack2(h2, h3);
        Lp.x = pack2(l0, l1); Lp.y = pack2(l2, l3);
        *reinterpret_cast<uint2*>(&Hh[row][kq]) = Hp;
        *reinterpret_cast<uint2*>(&Ll[row][kq]) = Lp;
    }
}

// 3xBF16 split GEMM (round-6/8 proven loop): C += A @ B^T, both [.][k] row-major.
__device__ __forceinline__ void gemm_bf3(
    const float* __restrict__ A, int lda,
    const float* __restrict__ Bm, int ldb,
    int kTiles, float acc[4][4][4],
    __nv_bfloat16 (*Ah)[AD], __nv_bfloat16 (*Al)[AD],
    __nv_bfloat16 (*Bh)[AD], __nv_bfloat16 (*Bl)[AD])
{
    const int tid  = threadIdx.x;
    const int lane = tid & 31, warp = tid >> 5;
    const int wm = (warp >> 2) * 64, wn = (warp & 3) * 32;

    const uint32_t aH = su32(&Ah[0][0]), aL = su32(&Al[0][0]);
    const uint32_t bH = su32(&Bh[0][0]), bL = su32(&Bl[0][0]);

    const int rowA = wm + ((lane >> 3) & 1) * 8 + (lane & 7);
    const int kcA  = (lane >> 4) * 8;
    const int rowB = (lane & 7);
    const int kcB  = ((lane >> 3) & 1) * 8;

    for (int kt = 0; kt < kTiles; kt++){
        load_tile_bf(A,  lda, kt*BK2, Ah, Al, tid);
        load_tile_bf(Bm, ldb, kt*BK2, Bh, Bl, tid);
        __syncthreads();

        #pragma unroll
        for (int s = 0; s < 2; s++){
            int kw = s * 16;
            uint32_t bh[4][2], bl[4][2];
            #pragma unroll
            for (int nt = 0; nt < 4; nt++){
                uint32_t off = (uint32_t)(((wn + nt*8 + rowB)*AD + kw + kcB) * 2);
                ldsm2(bh[nt], bH + off);
                ldsm2(bl[nt], bL + off);
            }
            #pragma unroll
            for (int mt = 0; mt < 4; mt++){
                uint32_t off = (uint32_t)(((rowA + mt*16)*AD + kw + kcA) * 2);
                uint32_t ah[4], al[4];
                ldsm4(ah, aH + off);
                ldsm4(al, aL + off);
                #pragma unroll
                for (int nt = 0; nt < 4; nt++){
                    mma16(acc[mt][nt], ah, bh[nt]);
                    mma16(acc[mt][nt], ah, bl[nt]);
                    mma16(acc[mt][nt], al, bh[nt]);
                }
            }
        }
        __syncthreads();
    }
}

// TF32 GEMM, cp.async double-buffered + ldmatrix fragments.
// A: (m,k) at A[m*lda+k] fp32; B: (n,k) at Bm[n*ldb+k] (pre-rounded tf32 ok).
// HW truncates fp32->tf32 on mma input (standard CUTLASS tf32 path).
__device__ __forceinline__ void gemm_tf32_cp(
    const float* __restrict__ A, int lda,
    const float* __restrict__ Bm, int ldb,
    int kTiles, float acc[4][4][4],
    float (*Asb)[128][TST], float (*Bsb)[128][TST])   // [2][128][20]
{
    const int tid  = threadIdx.x;
    const int lane = tid & 31, warp = tid >> 5;
    const int wm = (warp >> 2) * 64, wn = (warp & 3) * 32;

    const int crow = tid >> 2, csub = (tid & 3) * 4;          // cp.async chunk 0
    const int crow2 = crow + 64;                               // chunk 1 (tid+256)

    auto issue = [&](int kt){
        int st = kt & 1;
        cpa16(su32(&Asb[st][crow ][csub]), A  + (size_t)crow *lda + kt*TKT + csub);
        cpa16(su32(&Asb[st][crow2][csub]), A  + (size_t)crow2*lda + kt*TKT + csub);
        cpa16(su32(&Bsb[st][crow ][csub]), Bm + (size_t)crow *ldb + kt*TKT + csub);
        cpa16(su32(&Bsb[st][crow2][csub]), Bm + (size_t)crow2*ldb + kt*TKT + csub);
        cp_commit();
    };

    // ldmatrix lane address components (fp32-as-b16pair trick)
    const int arow = (lane & 15), acol = (lane >> 4) * 4;               // A x4
    const int brow = (lane & 7) + ((lane >> 4) * 8);                    // B x4 (2 nt)
    const int bcol = ((lane >> 3) & 1) * 4;

    issue(0);
    for (int kt = 0; kt < kTiles; kt++){
        if (kt + 1 < kTiles){ issue(kt+1); cp_wait<1>(); }
        else                 cp_wait<0>();
        __syncthreads();

        int st = kt & 1;
        const uint32_t aBase = su32(&Asb[st][0][0]);
        const uint32_t bBase = su32(&Bsb[st][0][0]);

        #pragma unroll
        for (int ks = 0; ks < 2; ks++){
            uint32_t bfv[2][4];
            #pragma unroll
            for (int np = 0; np < 2; np++){
                uint32_t ad = bBase + (uint32_t)(((wn + np*16 + brow)*TST + ks*8 + bcol)*4);
                ldsm4(bfv[np], ad);
            }
            #pragma unroll
            for (int mt = 0; mt < 4; mt++){
                uint32_t af[4];
                uint32_t ad = aBase + (uint32_t)(((wm + mt*16 + arow)*TST + ks*8 + acol)*4);
                ldsm4(af, ad);
                #pragma unroll
                for (int nt = 0; nt < 4; nt++)
                    mma8(acc[mt][nt], af, &bfv[nt>>1][(nt&1)*2]);
            }
        }
        __syncthreads();
    }
}

// ---------------- kernels ----------------

__global__ void __launch_bounds__(256) k_zero(){
    g_rowsum[blockIdx.x*blockDim.x + threadIdx.x] = 0.0f;
}

// Transpose weights: z<3 -> Wk/Wv/Wq -> g_WT[z] (fp32); z=3,4 -> Wf halves -> g_WfT (tf32-rounded)
__global__ void __launch_bounds__(256) k_tr(
    const float* __restrict__ Wk, const float* __restrict__ Wv,
    const float* __restrict__ Wq, const float* __restrict__ Wf)
{
    __shared__ float t[32][33];
    int z = blockIdx.z;
    const float* src; float* dst; int ldd, koff; bool rnd;
    if (z < 3){
        src = (z == 0) ? Wk : (z == 1 ? Wv : Wq);
        dst = g_WT + (size_t)z * H_ * H_;
        ldd = H_; koff = 0; rnd = false;
    } else {
        src = Wf + (size_t)(z-3) * H_ * H_;
        dst = g_WfT;
        ldd = 2*H_; koff = (z-3) * H_; rnd = true;
    }
    int x  = blockIdx.x*32 + threadIdx.x;   // n
    int y0 = blockIdx.y*32;                 // k
    #pragma unroll
    for (int j = 0; j < 4; j++)
        t[threadIdx.y + 8*j][threadIdx.x] = src[(size_t)(y0 + threadIdx.y + 8*j)*H_ + x];
    __syncthreads();
    #pragma unroll
    for (int j = 0; j < 4; j++){
        int n = blockIdx.x*32 + threadIdx.y + 8*j;
        float v = t[threadIdx.x][threadIdx.y + 8*j];
        dst[(size_t)n*ldd + koff + y0 + threadIdx.x] = rnd ? tf32r(v) : v;
    }
}

// Transpose V per (b,h): g_V[(b*S+s)][h*D+d] -> g_VT[((b*NH+h)*D+d)][s] (tf32-rounded)
__global__ void __launch_bounds__(256) k_trv()
{
    __shared__ float t[32][33];
    int z = blockIdx.z;                 // b*NH + h
    int b = z >> 2, h = z & 3;
    int d0 = blockIdx.x*32, s0 = blockIdx.y*32;
    #pragma unroll
    for (int j = 0; j < 4; j++)
        t[threadIdx.y + 8*j][threadIdx.x] =
            g_V[(size_t)(b*S_ + s0 + threadIdx.y + 8*j)*H_ + h*D_ + d0 + threadIdx.x];
    __syncthreads();
    #pragma unroll
    for (int j = 0; j < 4; j++)
        g_VT[((size_t)z*D_ + d0 + threadIdx.y + 8*j)*S_ + s0 + threadIdx.x] =
            tf32r(t[threadIdx.x][threadIdx.y + 8*j]);
}

// z=0: K = memory@Wk ; z=1: V = memory@Wv ; z=2: Q = decoder@Wq   (bf16x3)
__global__ void __launch_bounds__(256, 2) k_qkv(
    const float* __restrict__ mem, const float* __restrict__ dec)
{
    __shared__ __nv_bfloat16 Ah[128][AD], Al[128][AD], Bh[128][AD], Bl[128][AD];
    float acc[4][4][4] = {};

    int m0 = blockIdx.y * BM, n0 = blockIdx.x * BN;
    const float* A = (blockIdx.z == 2) ? dec : mem;
    float* C = (blockIdx.z == 0) ? g_K : (blockIdx.z == 1 ? g_V : g_Q);
    const float* Bt = g_WT + (size_t)blockIdx.z * H_ * H_ + (size_t)n0 * H_;

    gemm_bf3(A + (size_t)m0*H_, H_, Bt, H_, H_/BK2, acc, Ah, Al, Bh, Bl);

    const int lane = threadIdx.x & 31, warp = threadIdx.x >> 5;
    const int wm = (warp>>2)*64, wn = (warp&3)*32, g = lane>>2, cq = (lane&3)*2;
    #pragma unroll
    for (int mt = 0; mt < 4; mt++)
      #pragma unroll
      for (int nt = 0; nt < 4; nt++)
        #pragma unroll
        for (int r = 0; r < 4; r++){
            int rl = wm + mt*16 + g + ((r>>1)<<3);
            int cl = wn + nt*8 + cq + (r&1);
            C[(size_t)(m0+rl)*H_ + n0 + cl] = acc[mt][nt][r];
        }
}

// S = Q@K^T/16 - gauss ; mask -> p=0 ; p = exp(s) unnormalized -> attn (d_out); rowsum atomics
__global__ void __launch_bounds__(256, 2) k_score(
    const int* __restrict__ mask,
    const float* __restrict__ gfac,
    float* __restrict__ attn)
{
    __shared__ __nv_bfloat16 Ah[128][AD], Al[128][AD], Bh[128][AD], Bl[128][AD];
    float acc[4][4][4] = {};

    int hb = blockIdx.z, h = hb >> 3, b = hb & 7;
    int q0 = blockIdx.y * BM, n0 = blockIdx.x * BN;

    const float* Aq = g_Q + (size_t)(b*S_)*H_ + h*D_ + (size_t)q0*H_;
    const float* Bk = g_K + (size_t)(b*S_)*H_ + h*D_ + (size_t)n0*H_;
    gemm_bf3(Aq, H_, Bk, H_, D_/BK2, acc, Ah, Al, Bh, Bl);

    float inv_gf = 1.0f / gfac[0];
    float* out = attn + (size_t)hb * S_ * S_;
    const int* mrow = mask + (size_t)b * S_ * S_;

    const int lane = threadIdx.x & 31, warp = threadIdx.x >> 5;
    const int wm = (warp>>2)*64, wn = (warp&3)*32, g = lane>>2, cq = (lane&3)*2;
    #pragma unroll
    for (int mt = 0; mt < 4; mt++){
        float rs[2] = {0.0f, 0.0f};
        #pragma unroll
        for (int nt = 0; nt < 4; nt++)
            #pragma unroll
            for (int r = 0; r < 4; r++){
                int row = q0 + wm + mt*16 + g + ((r>>1)<<3);
                int col = n0 + wn + nt*8 + cq + (r&1);
                int dq  = row - col;
                float s = acc[mt][nt][r]*0.0625f - (float)(dq*dq)*inv_gf;
                float p = mrow[(size_t)row*S_ + col] ? 0.0f : __expf(s);
                out[(size_t)row*S_ + col] = p;
                rs[r>>1] += p;
            }
        #pragma unroll
        for (int j = 0; j < 2; j++){
            rs[j] += __shfl_xor_sync(0xffffffffu, rs[j], 1);
            rs[j] += __shfl_xor_sync(0xffffffffu, rs[j], 2);
        }
        if ((lane & 3) == 0){
            int rbase = hb*S_ + q0 + wm + mt*16 + g;
            atomicAdd(&g_rowsum[rbase    ], rs[0]);
            atomicAdd(&g_rowsum[rbase + 8], rs[1]);
        }
    }
}

// O = P@V (tf32 cp.async+ldsm, B = VT), epilogue scale by query_mask/rowsum -> g_res
__global__ void __launch_bounds__(256, 2) k_pv(
    const float* __restrict__ attn, const float* __restrict__ qm)
{
    __shared__ __align__(16) float Asb[2][128][TST];
    __shared__ __align__(16) float Bsb[2][128][TST];
    float acc[4][4][4] = {};

    int hb = blockIdx.z, h = hb >> 3, b = hb & 7;
    int q0 = blockIdx.y * BM, n0 = blockIdx.x * BN;   // n over D (2 blocks of 128)

    const float* Ap = attn + (size_t)hb*S_*S_ + (size_t)q0*S_;
    const float* Bv = g_VT + ((size_t)(b*NH_+h)*D_ + n0)*S_;
    gemm_tf32_cp(Ap, S_, Bv, S_, S_/TKT, acc, Asb, Bsb);

    const int lane = threadIdx.x & 31, warp = threadIdx.x >> 5;
    const int wm = (warp>>2)*64, wn = (warp&3)*32, g = lane>>2, cq = (lane&3)*2;
    #pragma unroll
    for (int mt = 0; mt < 4; mt++)
      #pragma unroll
      for (int r2 = 0; r2 < 2; r2++){
          int q  = q0 + wm + mt*16 + g + r2*8;
          float sc = qm[b*S_ + q] / g_rowsum[hb*S_ + q];
          #pragma unroll
          for (int nt = 0; nt < 4; nt++)
            #pragma unroll
            for (int rr = 0; rr < 2; rr++){
                int cl = wn + nt*8 + cq + rr;
                g_res[(size_t)(b*S_+q)*H_ + h*D_ + n0 + cl] = acc[mt][nt][r2*2+rr]*sc;
            }
      }
}

// attn *= query_mask[b,q] / rowsum[hb,q]   (in place, float4)
__global__ void __launch_bounds__(256) k_attn_norm(
    float* __restrict__ attn, const float* __restrict__ qm)
{
    size_t i = (size_t)blockIdx.x * blockDim.x + threadIdx.x;
    int rowi = (int)(i >> 8);
    int hb = rowi >> 10, q = rowi & 1023, b = hb & 7;
    float sc = qm[b*S_ + q] / g_rowsum[hb*S_ + q];
    float4 v = reinterpret_cast<float4*>(attn)[i];
    v.x *= sc; v.y *= sc; v.z *= sc; v.w *= sc;
    reinterpret_cast<float4*>(attn)[i] = v;
}

// out_pre_ln = [decoder | res] @ Wf + bf + decoder -> g_tmp  (tf32 cp.async+ldsm, B = Wf^T)
__global__ void __launch_bounds__(256, 2) k_final(
    const float* __restrict__ dec, const float* __restrict__ bfv)
{
    __shared__ __align__(16) float Asb[2][128][TST];
    __shared__ __align__(16) float Bsb[2][128][TST];
    float acc[4][4][4] = {};

    int m0 = blockIdx.y * BM, n0 = blockIdx.x * BN;
    gemm_tf32_cp(dec   + (size_t)m0*H_, H_, g_WfT + (size_t)n0*2*H_,      2*H_, H_/TKT, acc, Asb, Bsb);
    gemm_tf32_cp(g_res + (size_t)m0*H_, H_, g_WfT + (size_t)n0*2*H_ + H_, 2*H_, H_/TKT, acc, Asb, Bsb);

    const int lane = threadIdx.x & 31, warp = threadIdx.x >> 5;
    const int wm = (warp>>2)*64, wn = (warp&3)*32, g = lane>>2, cq = (lane&3)*2;
    #pragma unroll
    for (int mt = 0; mt < 4; mt++)
      #pragma unroll
      for (int nt = 0; nt < 4; nt++)
        #pragma unroll
        for (int r = 0; r < 4; r++){
            int rl = wm + mt*16 + g + ((r>>1)<<3);
            int cl = wn + nt*8 + cq + (r&1);
            size_t idx = (size_t)(m0+rl)*H_ + n0 + cl;
            g_tmp[idx] = acc[mt][nt][r] + bfv[n0+cl] + dec[idx];
        }
}

// per-row layernorm over H=1024 -> d_out
__global__ void __launch_bounds__(256) k_ln(
    const float* __restrict__ gam, const float* __restrict__ bet,
    float* __restrict__ out)
{
    __shared__ float red[8];
    int row = blockIdx.x, tid = threadIdx.x;
    float4 v = reinterpret_cast<const float4*>(g_tmp + (size_t)row*H_)[tid];
    float s = v.x + v.y + v.z + v.w;
    #pragma unroll
    for (int o = 16; o; o >>= 1) s += __shfl_xor_sync(0xffffffffu, s, o);
    if ((tid & 31) == 0) red[tid >> 5] = s;
    __syncthreads();
    float tot = 0.0f;
    #pragma unroll
    for (int i = 0; i < 8; i++) tot += red[i];
    float mu = tot * (1.0f/H_);
    float dx = v.x - mu, dy = v.y - mu, dz = v.z - mu, dw = v.w - mu;
    float s2 = dx*dx + dy*dy + dz*dz + dw*dw;
    #pragma unroll
    for (int o = 16; o; o >>= 1) s2 += __shfl_xor_sync(0xffffffffu, s2, o);
    __syncthreads();
    if ((tid & 31) == 0) red[tid >> 5] = s2;
    __syncthreads();
    float tot2 = 0.0f;
    #pragma unroll
    for (int i = 0; i < 8; i++) tot2 += red[i];
    float inv = rsqrtf(tot2 * (1.0f/H_) + 1e-5f);
    int c = tid * 4;
    float4 o4;
    o4.x = dx*inv*gam[c+0] + bet[c+0];
    o4.y = dy*inv*gam[c+1] + bet[c+1];
    o4.z = dz*inv*gam[c+2] + bet[c+2];
    o4.w = dw*inv*gam[c+3] + bet[c+3];
    reinterpret_cast<float4*>(out + (size_t)row*H_)[tid] = o4;
}

extern "C" void kernel_launch(void* const* d_in, const int* in_sizes, int n_in,
                              void* d_out, int out_size)
{
    (void)in_sizes; (void)n_in; (void)out_size;
    const float* memory = (const float*)d_in[0];
    const float* dec    = (const float*)d_in[1];
    const int*   mask   = (const int*)d_in[2];    // bool stored as int32
    const float* qmask  = (const float*)d_in[3];
    const float* Wk     = (const float*)d_in[4];
    const float* Wv     = (const float*)d_in[5];
    const float* Wq     = (const float*)d_in[6];
    const float* Wf     = (const float*)d_in[7];
    const float* bfv    = (const float*)d_in[8];
    const float* gamma  = (const float*)d_in[9];
    const float* beta   = (const float*)d_in[10];
    const float* gfac   = (const float*)d_in[11];

    float* out  = (float*)d_out;
    float* attn = out + OUT0;

    k_tr<<<dim3(32, 32, 5), dim3(32, 8)>>>(Wk, Wv, Wq, Wf);
    k_zero<<<128, 256>>>();
    k_qkv<<<dim3(8, 64, 3), 256>>>(memory, dec);
    k_trv<<<dim3(8, 32, 32), dim3(32, 8)>>>();
    k_score<<<dim3(8, 8, 32), 256>>>(mask, gfac, attn);
    k_pv<<<dim3(2, 8, 32), 256>>>(attn, qmask);
    k_attn_norm<<<32768, 256>>>(attn, qmask);
    k_final<<<dim3(8, 64), 256>>>(dec, bfv);
    k_ln<<<8192, 256>>>(gamma, beta, out);
}